// round 4
// baseline (speedup 1.0000x reference)
#include <cuda_runtime.h>

// Problem constants
#define BQ      16          // query rows per CTA
#define LSEQ    2048        // sequence length
#define DH      64          // head dim
#define CHUNK   64          // K/V rows staged per iteration
#define KSTR    68          // padded smem stride (floats) for K/V stage
#define NBH     64          // B*H
#define THREADS 256

// dynamic smem layout (floats):
//   S  [BQ][LSEQ]        : 32768 floats (scores -> probs)
//   Qs [BQ][DH]          : 1024 floats
//   Ks [CHUNK][KSTR]     : 4352 floats (K or V stage)
#define SMEM_FLOATS (BQ*LSEQ + BQ*DH + CHUNK*KSTR)
#define SMEM_BYTES  (SMEM_FLOATS * 4)

__global__ __launch_bounds__(THREADS, 1)
void sdpa_kernel(const float* __restrict__ Qg, const float* __restrict__ Kg,
                 const float* __restrict__ Vg, float* __restrict__ ctx,
                 float* __restrict__ attn)
{
    extern __shared__ float sm[];
    float* S  = sm;                    // BQ * LSEQ
    float* Qs = S + BQ * LSEQ;         // BQ * DH
    float* Ks = Qs + BQ * DH;          // CHUNK * KSTR

    const int tid = threadIdx.x;
    const int bh  = blockIdx.y;        // 0..63
    const int qt  = blockIdx.x;        // 0..127
    const long qbase  = ((long)bh * LSEQ + (long)qt * BQ) * DH;
    const long kvbase = (long)bh * LSEQ * DH;

    // ---- load Q tile (16 x 64) ----
    {
        int r  = tid >> 4;             // 0..15
        int d4 = (tid & 15) << 2;      // 0,4,...,60
        *(float4*)&Qs[r * DH + d4] = *(const float4*)&Qg[qbase + (long)r * DH + d4];
    }

    const int a = tid >> 6;            // 0..3  -> q rows 4a..4a+3
    const int j = tid & 63;            // 0..63 -> k column within chunk

    // ==================== Phase 1: S = Q @ K^T ====================
    for (int c0 = 0; c0 < LSEQ; c0 += CHUNK) {
        __syncthreads();               // previous compute done before restaging
        // stage K chunk [64 rows][64 d] into Ks (padded stride)
        #pragma unroll
        for (int it = 0; it < 4; ++it) {
            int idx = tid + it * THREADS;      // 0..1023
            int row = idx >> 4;
            int d4  = (idx & 15) << 2;
            *(float4*)&Ks[row * KSTR + d4] =
                *(const float4*)&Kg[kvbase + (long)(c0 + row) * DH + d4];
        }
        __syncthreads();

        float acc0 = 0.f, acc1 = 0.f, acc2 = 0.f, acc3 = 0.f;
        #pragma unroll
        for (int d = 0; d < DH; d += 4) {
            float4 kv = *(float4*)&Ks[j * KSTR + d];
            float4 q0 = *(float4*)&Qs[(4*a + 0) * DH + d];
            float4 q1 = *(float4*)&Qs[(4*a + 1) * DH + d];
            float4 q2 = *(float4*)&Qs[(4*a + 2) * DH + d];
            float4 q3 = *(float4*)&Qs[(4*a + 3) * DH + d];
            acc0 += q0.x*kv.x + q0.y*kv.y + q0.z*kv.z + q0.w*kv.w;
            acc1 += q1.x*kv.x + q1.y*kv.y + q1.z*kv.z + q1.w*kv.w;
            acc2 += q2.x*kv.x + q2.y*kv.y + q2.z*kv.z + q2.w*kv.w;
            acc3 += q3.x*kv.x + q3.y*kv.y + q3.z*kv.z + q3.w*kv.w;
        }
        S[(4*a + 0) * LSEQ + c0 + j] = acc0;
        S[(4*a + 1) * LSEQ + c0 + j] = acc1;
        S[(4*a + 2) * LSEQ + c0 + j] = acc2;
        S[(4*a + 3) * LSEQ + c0 + j] = acc3;
    }
    __syncthreads();

    // ==================== Phase 2: row softmax + write attn ====================
    {
        const int warp = tid >> 5;
        const int lane = tid & 31;
        #pragma unroll
        for (int rr = 0; rr < 2; ++rr) {
            const int r = warp * 2 + rr;       // 0..15
            float* Srow = S + r * LSEQ;

            float m = -1e30f;
            for (int c = lane; c < LSEQ; c += 32) m = fmaxf(m, Srow[c]);
            #pragma unroll
            for (int o = 16; o > 0; o >>= 1)
                m = fmaxf(m, __shfl_xor_sync(0xffffffffu, m, o));

            float sum = 0.f;
            for (int c = lane; c < LSEQ; c += 32) {
                float p = __expf(Srow[c] - m);
                Srow[c] = p;
                sum += p;
            }
            #pragma unroll
            for (int o = 16; o > 0; o >>= 1)
                sum += __shfl_xor_sync(0xffffffffu, sum, o);

            const float inv = 1.0f / sum;
            const long arow = ((long)bh * LSEQ + (long)qt * BQ + r) * LSEQ;
            for (int c = lane; c < LSEQ; c += 32) {
                float p = Srow[c] * inv;
                Srow[c] = p;
                attn[arow + c] = p;
            }
        }
    }

    // ==================== Phase 3: ctx = P @ V ====================
    {
        const int r3 = tid >> 4;               // 0..15
        const int dg = (tid & 15) << 2;        // 0,4,...,60
        float ax = 0.f, ay = 0.f, az = 0.f, aw = 0.f;

        for (int c0 = 0; c0 < LSEQ; c0 += CHUNK) {
            __syncthreads();                   // prior compute done before restaging
            #pragma unroll
            for (int it = 0; it < 4; ++it) {
                int idx = tid + it * THREADS;
                int row = idx >> 4;
                int d4  = (idx & 15) << 2;
                *(float4*)&Ks[row * KSTR + d4] =
                    *(const float4*)&Vg[kvbase + (long)(c0 + row) * DH + d4];
            }
            __syncthreads();

            #pragma unroll
            for (int kk = 0; kk < CHUNK; kk += 4) {
                float4 ps = *(float4*)&S[r3 * LSEQ + c0 + kk];
                float4 v0 = *(float4*)&Ks[(kk + 0) * KSTR + dg];
                float4 v1 = *(float4*)&Ks[(kk + 1) * KSTR + dg];
                float4 v2 = *(float4*)&Ks[(kk + 2) * KSTR + dg];
                float4 v3 = *(float4*)&Ks[(kk + 3) * KSTR + dg];
                ax += ps.x*v0.x + ps.y*v1.x + ps.z*v2.x + ps.w*v3.x;
                ay += ps.x*v0.y + ps.y*v1.y + ps.z*v2.y + ps.w*v3.y;
                az += ps.x*v0.z + ps.y*v1.z + ps.z*v2.z + ps.w*v3.z;
                aw += ps.x*v0.w + ps.y*v1.w + ps.z*v2.w + ps.w*v3.w;
            }
        }

        float4 out; out.x = ax; out.y = ay; out.z = az; out.w = aw;
        *(float4*)&ctx[qbase + (long)r3 * DH + dg] = out;
    }
}

extern "C" void kernel_launch(void* const* d_in, const int* in_sizes, int n_in,
                              void* d_out, int out_size)
{
    const float* Q = (const float*)d_in[0];
    const float* K = (const float*)d_in[1];
    const float* V = (const float*)d_in[2];

    float* ctx  = (float*)d_out;                                   // [B,H,L,D]
    float* attn = ctx + (size_t)NBH * LSEQ * DH;                   // [B,H,L,L]

    cudaFuncSetAttribute(sdpa_kernel,
                         cudaFuncAttributeMaxDynamicSharedMemorySize, SMEM_BYTES);

    dim3 grid(LSEQ / BQ, NBH);   // (128, 64)
    sdpa_kernel<<<grid, THREADS, SMEM_BYTES>>>(Q, K, V, ctx, attn);
}

// round 5
// speedup vs baseline: 1.9918x; 1.9918x over previous
#include <cuda_runtime.h>

// Problem constants
#define BQ      16          // query rows per CTA
#define LSEQ    2048        // sequence length
#define DH      64          // head dim
#define CHUNK   256         // K/V rows staged per iteration
#define NCHUNK  (LSEQ/CHUNK)
#define KSTR    68          // K/V stage row stride (words); 68 % 32 == 4 -> conflict-free
#define SSTR    2056        // S row stride (words); 2056 % 32 == 8 -> conflict-free P loads
#define NBH     64          // B*H
#define THREADS 256

// dynamic smem (floats): S[16][2056] + Qs[16][64] + Ks[256][68]
#define SMEM_FLOATS (BQ*SSTR + BQ*DH + CHUNK*KSTR)
#define SMEM_BYTES  (SMEM_FLOATS * 4)   // 205,312 B

__global__ __launch_bounds__(THREADS, 1)
void sdpa_kernel(const float* __restrict__ Qg, const float* __restrict__ Kg,
                 const float* __restrict__ Vg, float* __restrict__ ctx,
                 float* __restrict__ attn)
{
    extern __shared__ float sm[];
    float* S  = sm;                      // BQ * SSTR
    float* Qs = S + BQ * SSTR;           // BQ * DH
    float* Ks = Qs + BQ * DH;            // CHUNK * KSTR  (K stage / V stage / reduce scratch)

    const int tid = threadIdx.x;
    const int bh  = blockIdx.y;          // 0..63
    const int qt  = blockIdx.x;          // 0..127
    const long qbase  = ((long)bh * LSEQ + (long)qt * BQ) * DH;
    const long kvbase = (long)bh * LSEQ * DH;

    // ---- load Q tile (16 x 64): one float4 per thread ----
    {
        int r  = tid >> 4;               // 0..15
        int d4 = (tid & 15) << 2;        // 0..60
        *(float4*)&Qs[r * DH + d4] = *(const float4*)&Qg[qbase + (long)r * DH + d4];
    }

    float4 pre[16];                      // staging prefetch registers (one chunk)

    // prefetch K chunk 0
    #pragma unroll
    for (int it = 0; it < 16; ++it) {
        int idx = tid + it * THREADS;
        int row = idx >> 4, d4 = (idx & 15) << 2;
        pre[it] = *(const float4*)&Kg[kvbase + (long)row * DH + d4];
    }

    // ==================== Phase 1: S = Q @ K^T ====================
    // thread tile: 4 q rows {a, a+4, a+8, a+12} x 4 k cols {kg, kg+64, kg+128, kg+192}
    {
        const int a  = tid >> 6;         // 0..3
        const int kg = tid & 63;         // 0..63 (consecutive per lane -> conflict-free K LDS)

        for (int c0 = 0; c0 < LSEQ; c0 += CHUNK) {
            __syncthreads();             // Ks free (prev chunk consumed); Qs ready (1st iter)
            #pragma unroll
            for (int it = 0; it < 16; ++it) {
                int idx = tid + it * THREADS;
                int row = idx >> 4, d4 = (idx & 15) << 2;
                *(float4*)&Ks[row * KSTR + d4] = pre[it];
            }
            __syncthreads();

            if (c0 + CHUNK < LSEQ) {     // prefetch next chunk (hidden behind compute)
                #pragma unroll
                for (int it = 0; it < 16; ++it) {
                    int idx = tid + it * THREADS;
                    int row = idx >> 4, d4 = (idx & 15) << 2;
                    pre[it] = *(const float4*)&Kg[kvbase + (long)(c0 + CHUNK + row) * DH + d4];
                }
            }

            float acc[4][4] = {};
            #pragma unroll
            for (int d = 0; d < DH; d += 4) {
                float4 q[4], k[4];
                #pragma unroll
                for (int i = 0; i < 4; ++i)
                    q[i] = *(float4*)&Qs[(a + 4*i) * DH + d];        // warp-broadcast
                #pragma unroll
                for (int j = 0; j < 4; ++j)
                    k[j] = *(float4*)&Ks[(kg + 64*j) * KSTR + d];    // conflict-free
                #pragma unroll
                for (int i = 0; i < 4; ++i)
                    #pragma unroll
                    for (int j = 0; j < 4; ++j)
                        acc[i][j] += q[i].x*k[j].x + q[i].y*k[j].y
                                   + q[i].z*k[j].z + q[i].w*k[j].w;
            }
            #pragma unroll
            for (int i = 0; i < 4; ++i)
                #pragma unroll
                for (int j = 0; j < 4; ++j)
                    S[(a + 4*i) * SSTR + c0 + kg + 64*j] = acc[i][j];
        }
    }
    __syncthreads();

    // prefetch V chunk 0 now — latency hidden behind the softmax
    #pragma unroll
    for (int it = 0; it < 16; ++it) {
        int idx = tid + it * THREADS;
        int row = idx >> 4, d4 = (idx & 15) << 2;
        pre[it] = *(const float4*)&Vg[kvbase + (long)row * DH + d4];
    }

    // ==================== Phase 2: row softmax + write attn ====================
    {
        const int warp = tid >> 5;
        const int lane = tid & 31;
        #pragma unroll
        for (int rr = 0; rr < 2; ++rr) {
            const int r = warp * 2 + rr;             // 0..15
            float* Srow = S + r * SSTR;

            float m = -1e30f;
            for (int c = lane * 4; c < LSEQ; c += 128) {
                float4 v = *(float4*)&Srow[c];
                m = fmaxf(m, fmaxf(fmaxf(v.x, v.y), fmaxf(v.z, v.w)));
            }
            #pragma unroll
            for (int o = 16; o > 0; o >>= 1)
                m = fmaxf(m, __shfl_xor_sync(0xffffffffu, m, o));

            float sum = 0.f;
            for (int c = lane * 4; c < LSEQ; c += 128) {
                float4 v = *(float4*)&Srow[c];
                v.x = __expf(v.x - m); v.y = __expf(v.y - m);
                v.z = __expf(v.z - m); v.w = __expf(v.w - m);
                *(float4*)&Srow[c] = v;
                sum += (v.x + v.y) + (v.z + v.w);
            }
            #pragma unroll
            for (int o = 16; o > 0; o >>= 1)
                sum += __shfl_xor_sync(0xffffffffu, sum, o);

            const float inv = 1.0f / sum;
            const long arow = ((long)bh * LSEQ + (long)qt * BQ + r) * LSEQ;
            for (int c = lane * 4; c < LSEQ; c += 128) {
                float4 v = *(float4*)&Srow[c];
                v.x *= inv; v.y *= inv; v.z *= inv; v.w *= inv;
                *(float4*)&Srow[c] = v;
                *(float4*)&attn[arow + c] = v;
            }
        }
    }

    // ==================== Phase 3: ctx = P @ V ====================
    // warp = k-segment (8-way split); thread tile: rows {lq,lq+4,lq+8,lq+12} x
    // dims {4dg..4dg+3, 4dg+32..4dg+35}
    {
        const int ks = tid >> 5;         // 0..7: this warp's 32-key segment per chunk
        const int lq = (tid >> 3) & 3;   // 0..3
        const int dg = tid & 7;          // 0..7

        float4 accL[4] = {}, accH[4] = {};

        for (int c0 = 0; c0 < LSEQ; c0 += CHUNK) {
            __syncthreads();             // (1st iter: also ensures softmax complete)
            #pragma unroll
            for (int it = 0; it < 16; ++it) {
                int idx = tid + it * THREADS;
                int row = idx >> 4, d4 = (idx & 15) << 2;
                *(float4*)&Ks[row * KSTR + d4] = pre[it];
            }
            __syncthreads();

            if (c0 + CHUNK < LSEQ) {
                #pragma unroll
                for (int it = 0; it < 16; ++it) {
                    int idx = tid + it * THREADS;
                    int row = idx >> 4, d4 = (idx & 15) << 2;
                    pre[it] = *(const float4*)&Vg[kvbase + (long)(c0 + CHUNK + row) * DH + d4];
                }
            }

            #pragma unroll
            for (int kk = 0; kk < 32; kk += 4) {
                const int kb = ks * 32 + kk;
                float4 p[4];
                #pragma unroll
                for (int i = 0; i < 4; ++i)                       // conflict-free (SSTR%32==8)
                    p[i] = *(float4*)&S[(lq + 4*i) * SSTR + c0 + kb];
                #pragma unroll
                for (int t = 0; t < 4; ++t) {
                    float4 vL = *(float4*)&Ks[(kb + t) * KSTR + 4*dg];       // conflict-free
                    float4 vH = *(float4*)&Ks[(kb + t) * KSTR + 4*dg + 32];  // conflict-free
                    #pragma unroll
                    for (int i = 0; i < 4; ++i) {
                        const float pi = (t == 0) ? p[i].x : (t == 1) ? p[i].y
                                       : (t == 2) ? p[i].z : p[i].w;
                        accL[i].x += pi * vL.x; accL[i].y += pi * vL.y;
                        accL[i].z += pi * vL.z; accL[i].w += pi * vL.w;
                        accH[i].x += pi * vH.x; accH[i].y += pi * vH.y;
                        accH[i].z += pi * vH.z; accH[i].w += pi * vH.w;
                    }
                }
            }
        }

        // ---- cross-warp reduction of the 8 k-segments ----
        __syncthreads();                 // Ks stage no longer needed -> reuse as scratch
        float* P = Ks;                   // P[ks][row*68-ish]: stride 1088 floats per segment
        #pragma unroll
        for (int i = 0; i < 4; ++i) {
            const int row = lq + 4*i;
            *(float4*)&P[ks * 1088 + row * 68 + 4*dg     ] = accL[i];
            *(float4*)&P[ks * 1088 + row * 68 + 4*dg + 32] = accH[i];
        }
        __syncthreads();

        // each thread finalizes 4 consecutive output elements -> coalesced ctx write
        const int row = tid >> 4;                // 0..15
        const int dc  = (tid & 15) << 2;         // 0..60
        float4 s = {0.f, 0.f, 0.f, 0.f};
        #pragma unroll
        for (int w = 0; w < 8; ++w) {
            float4 v = *(float4*)&P[w * 1088 + row * 68 + dc];
            s.x += v.x; s.y += v.y; s.z += v.z; s.w += v.w;
        }
        *(float4*)&ctx[qbase + (long)row * DH + dc] = s;
    }
}

extern "C" void kernel_launch(void* const* d_in, const int* in_sizes, int n_in,
                              void* d_out, int out_size)
{
    const float* Q = (const float*)d_in[0];
    const float* K = (const float*)d_in[1];
    const float* V = (const float*)d_in[2];

    float* ctx  = (float*)d_out;                                   // [B,H,L,D]
    float* attn = ctx + (size_t)NBH * LSEQ * DH;                   // [B,H,L,L]

    cudaFuncSetAttribute(sdpa_kernel,
                         cudaFuncAttributeMaxDynamicSharedMemorySize, SMEM_BYTES);

    dim3 grid(LSEQ / BQ, NBH);   // (128, 64)
    sdpa_kernel<<<grid, THREADS, SMEM_BYTES>>>(Q, K, V, ctx, attn);
}

// round 7
// speedup vs baseline: 2.1705x; 1.0897x over previous
#include <cuda_runtime.h>
#include <cuda_bf16.h>

#define BQ      16
#define LSEQ    2048
#define DH      64
#define CHUNK   256
#define SSTR    2056        // S row stride (words)
#define QSTR    72          // Q/K/V bf16 row stride (elements); 36 words -> conflict-free frags
#define NBH     64
#define THREADS 256

// smem (bytes): S[16][2056] f32 = 131584 ; Qhi/Qlo[16][72] bf16 = 4608 ;
//               Khi/Klo[256][72] bf16 = 73728  -> total 209920
#define SMEM_BYTES (BQ*SSTR*4 + 2*BQ*QSTR*2 + 2*CHUNK*QSTR*2)

__device__ __forceinline__ unsigned short bits(__nv_bfloat16 h) {
    return *reinterpret_cast<unsigned short*>(&h);
}

// split fp32 -> (hi, lo) bf16 pairs, 4 at a time, packed 2-per-uint
__device__ __forceinline__ void split4(float4 v, uint2& hi, uint2& lo) {
    __nv_bfloat16 h0 = __float2bfloat16_rn(v.x);
    __nv_bfloat16 h1 = __float2bfloat16_rn(v.y);
    __nv_bfloat16 h2 = __float2bfloat16_rn(v.z);
    __nv_bfloat16 h3 = __float2bfloat16_rn(v.w);
    __nv_bfloat16 l0 = __float2bfloat16_rn(v.x - __bfloat162float(h0));
    __nv_bfloat16 l1 = __float2bfloat16_rn(v.y - __bfloat162float(h1));
    __nv_bfloat16 l2 = __float2bfloat16_rn(v.z - __bfloat162float(h2));
    __nv_bfloat16 l3 = __float2bfloat16_rn(v.w - __bfloat162float(h3));
    hi.x = (unsigned)bits(h0) | ((unsigned)bits(h1) << 16);
    hi.y = (unsigned)bits(h2) | ((unsigned)bits(h3) << 16);
    lo.x = (unsigned)bits(l0) | ((unsigned)bits(l1) << 16);
    lo.y = (unsigned)bits(l2) | ((unsigned)bits(l3) << 16);
}

__device__ __forceinline__ void mma16816(float* d, const unsigned* a,
                                         unsigned b0, unsigned b1) {
    asm volatile(
        "mma.sync.aligned.m16n8k16.row.col.f32.bf16.bf16.f32 "
        "{%0,%1,%2,%3}, {%4,%5,%6,%7}, {%8,%9}, {%0,%1,%2,%3};"
        : "+f"(d[0]), "+f"(d[1]), "+f"(d[2]), "+f"(d[3])
        : "r"(a[0]), "r"(a[1]), "r"(a[2]), "r"(a[3]), "r"(b0), "r"(b1));
}

__global__ __launch_bounds__(THREADS, 1)
void sdpa_kernel(const float* __restrict__ Qg, const float* __restrict__ Kg,
                 const float* __restrict__ Vg, float* __restrict__ ctx,
                 float* __restrict__ attn)
{
    extern __shared__ float sm[];
    float*          S   = sm;                                    // 16 x 2056 f32
    __nv_bfloat16*  Qhi = (__nv_bfloat16*)(S + BQ * SSTR);       // 16 x 72
    __nv_bfloat16*  Qlo = Qhi + BQ * QSTR;
    __nv_bfloat16*  Khi = Qlo + BQ * QSTR;                       // 256 x 72 (K or V stage)
    __nv_bfloat16*  Klo = Khi + CHUNK * QSTR;

    const int tid  = threadIdx.x;
    const int bh   = blockIdx.y;
    const int qt   = blockIdx.x;
    const long qbase  = ((long)bh * LSEQ + (long)qt * BQ) * DH;
    const long kvbase = (long)bh * LSEQ * DH;

    const int warp = tid >> 5;
    const int lane = tid & 31;
    const int g    = lane >> 2;     // 0..7
    const int tg   = lane & 3;      // 0..3

    // ---- stage Q: split into hi/lo bf16 planes ----
    {
        int r  = tid >> 4;
        int d4 = (tid & 15) << 2;
        float4 v = *(const float4*)&Qg[qbase + (long)r * DH + d4];
        uint2 hi, lo; split4(v, hi, lo);
        *(uint2*)&Qhi[r * QSTR + d4] = hi;
        *(uint2*)&Qlo[r * QSTR + d4] = lo;
    }

    float4 pre[16];
    #pragma unroll
    for (int it = 0; it < 16; ++it) {
        int idx = tid + it * THREADS;
        int row = idx >> 4, d4 = (idx & 15) << 2;
        pre[it] = *(const float4*)&Kg[kvbase + (long)row * DH + d4];
    }

    // ==================== Phase 1: S = Q @ K^T  (bf16-split MMA) ====================
    for (int c0 = 0; c0 < LSEQ; c0 += CHUNK) {
        __syncthreads();
        #pragma unroll
        for (int it = 0; it < 16; ++it) {
            int idx = tid + it * THREADS;
            int row = idx >> 4, d4 = (idx & 15) << 2;
            uint2 hi, lo; split4(pre[it], hi, lo);
            *(uint2*)&Khi[row * QSTR + d4] = hi;
            *(uint2*)&Klo[row * QSTR + d4] = lo;
        }
        __syncthreads();

        if (c0 + CHUNK < LSEQ) {
            #pragma unroll
            for (int it = 0; it < 16; ++it) {
                int idx = tid + it * THREADS;
                int row = idx >> 4, d4 = (idx & 15) << 2;
                pre[it] = *(const float4*)&Kg[kvbase + (long)(c0 + CHUNK + row) * DH + d4];
            }
        }

        float acc[4][4] = {};
        #pragma unroll
        for (int ks = 0; ks < 4; ++ks) {
            const int ko = ks * 16;
            unsigned ah[4], al[4];
            ah[0] = *(unsigned*)&Qhi[ g      * QSTR + ko + tg*2    ];
            ah[1] = *(unsigned*)&Qhi[(g + 8) * QSTR + ko + tg*2    ];
            ah[2] = *(unsigned*)&Qhi[ g      * QSTR + ko + tg*2 + 8];
            ah[3] = *(unsigned*)&Qhi[(g + 8) * QSTR + ko + tg*2 + 8];
            al[0] = *(unsigned*)&Qlo[ g      * QSTR + ko + tg*2    ];
            al[1] = *(unsigned*)&Qlo[(g + 8) * QSTR + ko + tg*2    ];
            al[2] = *(unsigned*)&Qlo[ g      * QSTR + ko + tg*2 + 8];
            al[3] = *(unsigned*)&Qlo[(g + 8) * QSTR + ko + tg*2 + 8];
            #pragma unroll
            for (int nt = 0; nt < 4; ++nt) {
                const int krow = warp * 32 + nt * 8 + g;
                unsigned bh0 = *(unsigned*)&Khi[krow * QSTR + ko + tg*2    ];
                unsigned bh1 = *(unsigned*)&Khi[krow * QSTR + ko + tg*2 + 8];
                unsigned bl0 = *(unsigned*)&Klo[krow * QSTR + ko + tg*2    ];
                unsigned bl1 = *(unsigned*)&Klo[krow * QSTR + ko + tg*2 + 8];
                mma16816(acc[nt], ah, bh0, bh1);   // hi*hi
                mma16816(acc[nt], ah, bl0, bl1);   // hi*lo
                mma16816(acc[nt], al, bh0, bh1);   // lo*hi
            }
        }
        #pragma unroll
        for (int nt = 0; nt < 4; ++nt) {
            const int col = c0 + warp * 32 + nt * 8 + tg * 2;
            *(float2*)&S[ g      * SSTR + col] = make_float2(acc[nt][0], acc[nt][1]);
            *(float2*)&S[(g + 8) * SSTR + col] = make_float2(acc[nt][2], acc[nt][3]);
        }
    }
    __syncthreads();

    // prefetch V chunk 0 (hidden behind softmax)
    #pragma unroll
    for (int it = 0; it < 16; ++it) {
        int idx = tid + it * THREADS;
        int row = idx >> 4, d4 = (idx & 15) << 2;
        pre[it] = *(const float4*)&Vg[kvbase + (long)row * DH + d4];
    }

    // ==================== Phase 2: softmax; write attn; pack P hi/lo in place ====================
    #pragma unroll
    for (int rr = 0; rr < 2; ++rr) {
        const int r = warp * 2 + rr;
        float* Srow = S + r * SSTR;

        float m = -1e30f;
        for (int c = lane * 4; c < LSEQ; c += 128) {
            float4 v = *(float4*)&Srow[c];
            m = fmaxf(m, fmaxf(fmaxf(v.x, v.y), fmaxf(v.z, v.w)));
        }
        #pragma unroll
        for (int o = 16; o > 0; o >>= 1)
            m = fmaxf(m, __shfl_xor_sync(0xffffffffu, m, o));

        float sum = 0.f;
        for (int c = lane * 4; c < LSEQ; c += 128) {
            float4 v = *(float4*)&Srow[c];
            v.x = __expf(v.x - m); v.y = __expf(v.y - m);
            v.z = __expf(v.z - m); v.w = __expf(v.w - m);
            *(float4*)&Srow[c] = v;
            sum += (v.x + v.y) + (v.z + v.w);
        }
        #pragma unroll
        for (int o = 16; o > 0; o >>= 1)
            sum += __shfl_xor_sync(0xffffffffu, sum, o);

        const float inv = 1.0f / sum;
        const long arow = ((long)bh * LSEQ + (long)qt * BQ + r) * LSEQ;
        for (int c = lane * 4; c < LSEQ; c += 128) {
            float4 v = *(float4*)&Srow[c];
            v.x *= inv; v.y *= inv; v.z *= inv; v.w *= inv;
            *(float4*)&attn[arow + c] = v;
            // pack (hi, lo) bf16 per element, overwrite the same words in S
            uint2 hA, lA; split4(v, hA, lA);
            uint4 pk;
            pk.x = (hA.x & 0xffffu) | (lA.x << 16);
            pk.y = (hA.x >> 16)     | (lA.x & 0xffff0000u);
            pk.z = (hA.y & 0xffffu) | (lA.y << 16);
            pk.w = (hA.y >> 16)     | (lA.y & 0xffff0000u);
            *(uint4*)&Srow[c] = pk;
        }
    }

    // ==================== Phase 3: ctx = P @ V  (bf16-split MMA, k-split warps) ====================
    float acc[8][4] = {};
    const unsigned short* Vhb = (const unsigned short*)Khi;
    const unsigned short* Vlb = (const unsigned short*)Klo;

    for (int c0 = 0; c0 < LSEQ; c0 += CHUNK) {
        __syncthreads();
        #pragma unroll
        for (int it = 0; it < 16; ++it) {
            int idx = tid + it * THREADS;
            int row = idx >> 4, d4 = (idx & 15) << 2;
            uint2 hi, lo; split4(pre[it], hi, lo);
            *(uint2*)&Khi[row * QSTR + d4] = hi;
            *(uint2*)&Klo[row * QSTR + d4] = lo;
        }
        __syncthreads();

        if (c0 + CHUNK < LSEQ) {
            #pragma unroll
            for (int it = 0; it < 16; ++it) {
                int idx = tid + it * THREADS;
                int row = idx >> 4, d4 = (idx & 15) << 2;
                pre[it] = *(const float4*)&Vg[kvbase + (long)(c0 + CHUNK + row) * DH + d4];
            }
        }

        #pragma unroll
        for (int rep = 0; rep < 2; ++rep) {
            const int l  = warp + rep * 8;       // kstep within chunk (16 keys)
            const int kb = l * 16;               // key offset in chunk
            const int col = c0 + kb;

            // A (P) fragments from packed S words: word = hi | (lo<<16)
            uint2 w0 = *(uint2*)&S[ g      * SSTR + col + tg*2    ];
            uint2 w1 = *(uint2*)&S[(g + 8) * SSTR + col + tg*2    ];
            uint2 w2 = *(uint2*)&S[ g      * SSTR + col + tg*2 + 8];
            uint2 w3 = *(uint2*)&S[(g + 8) * SSTR + col + tg*2 + 8];
            unsigned ah[4], al[4];
            ah[0] = __byte_perm(w0.x, w0.y, 0x5410); al[0] = __byte_perm(w0.x, w0.y, 0x7632);
            ah[1] = __byte_perm(w1.x, w1.y, 0x5410); al[1] = __byte_perm(w1.x, w1.y, 0x7632);
            ah[2] = __byte_perm(w2.x, w2.y, 0x5410); al[2] = __byte_perm(w2.x, w2.y, 0x7632);
            ah[3] = __byte_perm(w3.x, w3.y, 0x5410); al[3] = __byte_perm(w3.x, w3.y, 0x7632);

            #pragma unroll
            for (int nt = 0; nt < 8; ++nt) {
                const int dim = nt * 8 + g;
                const int k0  = (kb + tg * 2) * QSTR + dim;       // key tg*2
                const int k1  = k0 + QSTR;                        // key tg*2+1
                const int k8  = k0 + 8 * QSTR;                    // key tg*2+8
                const int k9  = k8 + QSTR;
                unsigned bh0 = (unsigned)Vhb[k0] | ((unsigned)Vhb[k1] << 16);
                unsigned bh1 = (unsigned)Vhb[k8] | ((unsigned)Vhb[k9] << 16);
                unsigned bl0 = (unsigned)Vlb[k0] | ((unsigned)Vlb[k1] << 16);
                unsigned bl1 = (unsigned)Vlb[k8] | ((unsigned)Vlb[k9] << 16);
                mma16816(acc[nt], ah, bh0, bh1);   // Phi*Vhi
                mma16816(acc[nt], ah, bl0, bl1);   // Phi*Vlo
                mma16816(acc[nt], al, bh0, bh1);   // Plo*Vhi
            }
        }
    }

    // ---- cross-warp reduction of 8 k-split segments ----
    __syncthreads();
    float* scr = (float*)Khi;                    // 8 segs x 16 rows x 68 stride
    #pragma unroll
    for (int nt = 0; nt < 8; ++nt) {
        const int d2 = nt * 8 + tg * 2;
        *(float2*)&scr[warp * 1088 +  g      * 68 + d2] = make_float2(acc[nt][0], acc[nt][1]);
        *(float2*)&scr[warp * 1088 + (g + 8) * 68 + d2] = make_float2(acc[nt][2], acc[nt][3]);
    }
    __syncthreads();

    {
        const int row = tid >> 4;
        const int dc  = (tid & 15) << 2;
        float4 s = {0.f, 0.f, 0.f, 0.f};
        #pragma unroll
        for (int w = 0; w < 8; ++w) {
            float4 v = *(float4*)&scr[w * 1088 + row * 68 + dc];
            s.x += v.x; s.y += v.y; s.z += v.z; s.w += v.w;
        }
        *(float4*)&ctx[qbase + (long)row * DH + dc] = s;
    }
}

extern "C" void kernel_launch(void* const* d_in, const int* in_sizes, int n_in,
                              void* d_out, int out_size)
{
    const float* Q = (const float*)d_in[0];
    const float* K = (const float*)d_in[1];
    const float* V = (const float*)d_in[2];

    float* ctx  = (float*)d_out;                         // [B,H,L,D]
    float* attn = ctx + (size_t)NBH * LSEQ * DH;         // [B,H,L,L]

    cudaFuncSetAttribute(sdpa_kernel,
                         cudaFuncAttributeMaxDynamicSharedMemorySize, SMEM_BYTES);

    dim3 grid(LSEQ / BQ, NBH);
    sdpa_kernel<<<grid, THREADS, SMEM_BYTES>>>(Q, K, V, ctx, attn);
}

// round 8
// speedup vs baseline: 2.3008x; 1.0600x over previous
#include <cuda_runtime.h>
#include <cuda_bf16.h>

#define BQ      16
#define LSEQ    2048
#define DH      64
#define CHUNK   256
#define SSTR    2056        // S row stride (words)
#define QSTR    72          // Q/K/V bf16 row stride (elements)
#define NBH     64
#define THREADS 512

// smem (bytes): S[16][2056] f32 ; Qhi/Qlo[16][72] bf16 ; Khi/Klo[256][72] bf16
#define SMEM_BYTES (BQ*SSTR*4 + 2*BQ*QSTR*2 + 2*CHUNK*QSTR*2)   // 209920

__device__ __forceinline__ unsigned short bits(__nv_bfloat16 h) {
    return *reinterpret_cast<unsigned short*>(&h);
}

__device__ __forceinline__ void split4(float4 v, uint2& hi, uint2& lo) {
    __nv_bfloat16 h0 = __float2bfloat16_rn(v.x);
    __nv_bfloat16 h1 = __float2bfloat16_rn(v.y);
    __nv_bfloat16 h2 = __float2bfloat16_rn(v.z);
    __nv_bfloat16 h3 = __float2bfloat16_rn(v.w);
    __nv_bfloat16 l0 = __float2bfloat16_rn(v.x - __bfloat162float(h0));
    __nv_bfloat16 l1 = __float2bfloat16_rn(v.y - __bfloat162float(h1));
    __nv_bfloat16 l2 = __float2bfloat16_rn(v.z - __bfloat162float(h2));
    __nv_bfloat16 l3 = __float2bfloat16_rn(v.w - __bfloat162float(h3));
    hi.x = (unsigned)bits(h0) | ((unsigned)bits(h1) << 16);
    hi.y = (unsigned)bits(h2) | ((unsigned)bits(h3) << 16);
    lo.x = (unsigned)bits(l0) | ((unsigned)bits(l1) << 16);
    lo.y = (unsigned)bits(l2) | ((unsigned)bits(l3) << 16);
}

__device__ __forceinline__ void mma16816(float* d, const unsigned* a,
                                         unsigned b0, unsigned b1) {
    asm volatile(
        "mma.sync.aligned.m16n8k16.row.col.f32.bf16.bf16.f32 "
        "{%0,%1,%2,%3}, {%4,%5,%6,%7}, {%8,%9}, {%0,%1,%2,%3};"
        : "+f"(d[0]), "+f"(d[1]), "+f"(d[2]), "+f"(d[3])
        : "r"(a[0]), "r"(a[1]), "r"(a[2]), "r"(a[3]), "r"(b0), "r"(b1));
}

__device__ __forceinline__ void ldsm4t(unsigned* r, const void* p) {
    unsigned addr = (unsigned)__cvta_generic_to_shared(p);
    asm volatile(
        "ldmatrix.sync.aligned.m8n8.x4.trans.shared.b16 {%0,%1,%2,%3}, [%4];"
        : "=r"(r[0]), "=r"(r[1]), "=r"(r[2]), "=r"(r[3]) : "r"(addr));
}

__global__ __launch_bounds__(THREADS, 1)
void sdpa_kernel(const float* __restrict__ Qg, const float* __restrict__ Kg,
                 const float* __restrict__ Vg, float* __restrict__ ctx,
                 float* __restrict__ attn)
{
    extern __shared__ float sm[];
    float*          S   = sm;                                    // 16 x 2056 f32
    __nv_bfloat16*  Qhi = (__nv_bfloat16*)(S + BQ * SSTR);       // 16 x 72
    __nv_bfloat16*  Qlo = Qhi + BQ * QSTR;
    __nv_bfloat16*  Khi = Qlo + BQ * QSTR;                       // 256 x 72 (K or V stage)
    __nv_bfloat16*  Klo = Khi + CHUNK * QSTR;

    const int tid  = threadIdx.x;
    const int bh   = blockIdx.y;
    const int qt   = blockIdx.x;
    const long qbase  = ((long)bh * LSEQ + (long)qt * BQ) * DH;
    const long kvbase = (long)bh * LSEQ * DH;

    const int warp = tid >> 5;      // 0..15
    const int lane = tid & 31;
    const int g    = lane >> 2;     // 0..7
    const int tg   = lane & 3;      // 0..3

    // ---- stage Q: split into hi/lo bf16 planes (first 256 threads) ----
    if (tid < 256) {
        int r  = tid >> 4;
        int d4 = (tid & 15) << 2;
        float4 v = *(const float4*)&Qg[qbase + (long)r * DH + d4];
        uint2 hi, lo; split4(v, hi, lo);
        *(uint2*)&Qhi[r * QSTR + d4] = hi;
        *(uint2*)&Qlo[r * QSTR + d4] = lo;
    }

    float4 pre[8];
    #pragma unroll
    for (int it = 0; it < 8; ++it) {
        int idx = tid + it * THREADS;
        int row = idx >> 4, d4 = (idx & 15) << 2;
        pre[it] = *(const float4*)&Kg[kvbase + (long)row * DH + d4];
    }

    // ==================== Phase 1: S = Q @ K^T  (bf16-split MMA) ====================
    // warp owns 16 keys per chunk: kb1 = warp*16
    {
        const int kb1 = warp * 16;
        for (int c0 = 0; c0 < LSEQ; c0 += CHUNK) {
            __syncthreads();
            #pragma unroll
            for (int it = 0; it < 8; ++it) {
                int idx = tid + it * THREADS;
                int row = idx >> 4, d4 = (idx & 15) << 2;
                uint2 hi, lo; split4(pre[it], hi, lo);
                *(uint2*)&Khi[row * QSTR + d4] = hi;
                *(uint2*)&Klo[row * QSTR + d4] = lo;
            }
            __syncthreads();

            if (c0 + CHUNK < LSEQ) {
                #pragma unroll
                for (int it = 0; it < 8; ++it) {
                    int idx = tid + it * THREADS;
                    int row = idx >> 4, d4 = (idx & 15) << 2;
                    pre[it] = *(const float4*)&Kg[kvbase + (long)(c0 + CHUNK + row) * DH + d4];
                }
            }

            float acc[2][4] = {};
            #pragma unroll
            for (int ks = 0; ks < 4; ++ks) {
                const int ko = ks * 16;
                unsigned ah[4], al[4];
                ah[0] = *(unsigned*)&Qhi[ g      * QSTR + ko + tg*2    ];
                ah[1] = *(unsigned*)&Qhi[(g + 8) * QSTR + ko + tg*2    ];
                ah[2] = *(unsigned*)&Qhi[ g      * QSTR + ko + tg*2 + 8];
                ah[3] = *(unsigned*)&Qhi[(g + 8) * QSTR + ko + tg*2 + 8];
                al[0] = *(unsigned*)&Qlo[ g      * QSTR + ko + tg*2    ];
                al[1] = *(unsigned*)&Qlo[(g + 8) * QSTR + ko + tg*2    ];
                al[2] = *(unsigned*)&Qlo[ g      * QSTR + ko + tg*2 + 8];
                al[3] = *(unsigned*)&Qlo[(g + 8) * QSTR + ko + tg*2 + 8];
                #pragma unroll
                for (int nt = 0; nt < 2; ++nt) {
                    const int krow = kb1 + nt * 8 + g;
                    unsigned bh0 = *(unsigned*)&Khi[krow * QSTR + ko + tg*2    ];
                    unsigned bh1 = *(unsigned*)&Khi[krow * QSTR + ko + tg*2 + 8];
                    unsigned bl0 = *(unsigned*)&Klo[krow * QSTR + ko + tg*2    ];
                    unsigned bl1 = *(unsigned*)&Klo[krow * QSTR + ko + tg*2 + 8];
                    mma16816(acc[nt], ah, bh0, bh1);
                    mma16816(acc[nt], ah, bl0, bl1);
                    mma16816(acc[nt], al, bh0, bh1);
                }
            }
            #pragma unroll
            for (int nt = 0; nt < 2; ++nt) {
                const int col = c0 + kb1 + nt * 8 + tg * 2;
                *(float2*)&S[ g      * SSTR + col] = make_float2(acc[nt][0], acc[nt][1]);
                *(float2*)&S[(g + 8) * SSTR + col] = make_float2(acc[nt][2], acc[nt][3]);
            }
        }
    }
    __syncthreads();

    // prefetch V chunk 0 (hidden behind softmax)
    #pragma unroll
    for (int it = 0; it < 8; ++it) {
        int idx = tid + it * THREADS;
        int row = idx >> 4, d4 = (idx & 15) << 2;
        pre[it] = *(const float4*)&Vg[kvbase + (long)row * DH + d4];
    }

    // ==================== Phase 2: softmax (1 row per warp); pack P hi|lo in place ====================
    {
        const int r = warp;                  // 0..15
        float* Srow = S + r * SSTR;

        float m = -1e30f;
        for (int c = lane * 4; c < LSEQ; c += 128) {
            float4 v = *(float4*)&Srow[c];
            m = fmaxf(m, fmaxf(fmaxf(v.x, v.y), fmaxf(v.z, v.w)));
        }
        #pragma unroll
        for (int o = 16; o > 0; o >>= 1)
            m = fmaxf(m, __shfl_xor_sync(0xffffffffu, m, o));

        float sum = 0.f;
        for (int c = lane * 4; c < LSEQ; c += 128) {
            float4 v = *(float4*)&Srow[c];
            v.x = __expf(v.x - m); v.y = __expf(v.y - m);
            v.z = __expf(v.z - m); v.w = __expf(v.w - m);
            *(float4*)&Srow[c] = v;
            sum += (v.x + v.y) + (v.z + v.w);
        }
        #pragma unroll
        for (int o = 16; o > 0; o >>= 1)
            sum += __shfl_xor_sync(0xffffffffu, sum, o);

        const float inv = 1.0f / sum;
        const long arow = ((long)bh * LSEQ + (long)qt * BQ + r) * LSEQ;
        for (int c = lane * 4; c < LSEQ; c += 128) {
            float4 v = *(float4*)&Srow[c];
            v.x *= inv; v.y *= inv; v.z *= inv; v.w *= inv;
            *(float4*)&attn[arow + c] = v;
            uint2 hA, lA; split4(v, hA, lA);
            uint4 pk;
            pk.x = (hA.x & 0xffffu) | (lA.x << 16);
            pk.y = (hA.x >> 16)     | (lA.x & 0xffff0000u);
            pk.z = (hA.y & 0xffffu) | (lA.y << 16);
            pk.w = (hA.y >> 16)     | (lA.y & 0xffff0000u);
            *(uint4*)&Srow[c] = pk;
        }
    }

    // ==================== Phase 3: ctx = P @ V  (16-way k-split, ldmatrix B frags) ====================
    float acc[8][4] = {};
    {
        const int kb = warp * 16;            // warp's 16-key segment within chunk
        // per-lane ldmatrix row address components
        const int lrow = kb + (lane & 15);           // key row for this lane
        const int lcol = (lane >> 4) * 8;            // +0 or +8 dim offset

        for (int c0 = 0; c0 < LSEQ; c0 += CHUNK) {
            __syncthreads();
            #pragma unroll
            for (int it = 0; it < 8; ++it) {
                int idx = tid + it * THREADS;
                int row = idx >> 4, d4 = (idx & 15) << 2;
                uint2 hi, lo; split4(pre[it], hi, lo);
                *(uint2*)&Khi[row * QSTR + d4] = hi;
                *(uint2*)&Klo[row * QSTR + d4] = lo;
            }
            __syncthreads();

            if (c0 + CHUNK < LSEQ) {
                #pragma unroll
                for (int it = 0; it < 8; ++it) {
                    int idx = tid + it * THREADS;
                    int row = idx >> 4, d4 = (idx & 15) << 2;
                    pre[it] = *(const float4*)&Vg[kvbase + (long)(c0 + CHUNK + row) * DH + d4];
                }
            }

            const int col = c0 + kb;
            // A (P) fragments from packed S words: word = hi | (lo<<16)
            uint2 w0 = *(uint2*)&S[ g      * SSTR + col + tg*2    ];
            uint2 w1 = *(uint2*)&S[(g + 8) * SSTR + col + tg*2    ];
            uint2 w2 = *(uint2*)&S[ g      * SSTR + col + tg*2 + 8];
            uint2 w3 = *(uint2*)&S[(g + 8) * SSTR + col + tg*2 + 8];
            unsigned ah[4], al[4];
            ah[0] = __byte_perm(w0.x, w0.y, 0x5410); al[0] = __byte_perm(w0.x, w0.y, 0x7632);
            ah[1] = __byte_perm(w1.x, w1.y, 0x5410); al[1] = __byte_perm(w1.x, w1.y, 0x7632);
            ah[2] = __byte_perm(w2.x, w2.y, 0x5410); al[2] = __byte_perm(w2.x, w2.y, 0x7632);
            ah[3] = __byte_perm(w3.x, w3.y, 0x5410); al[3] = __byte_perm(w3.x, w3.y, 0x7632);

            #pragma unroll
            for (int dp = 0; dp < 4; ++dp) {
                const int d0 = dp * 16;
                unsigned hb[4], lb[4];
                ldsm4t(hb, &Khi[lrow * QSTR + d0 + lcol]);
                ldsm4t(lb, &Klo[lrow * QSTR + d0 + lcol]);
                // n-group dims d0..d0+7 -> acc[2dp]; d0+8..d0+15 -> acc[2dp+1]
                mma16816(acc[2*dp    ], ah, hb[0], hb[1]);
                mma16816(acc[2*dp    ], ah, lb[0], lb[1]);
                mma16816(acc[2*dp    ], al, hb[0], hb[1]);
                mma16816(acc[2*dp + 1], ah, hb[2], hb[3]);
                mma16816(acc[2*dp + 1], ah, lb[2], lb[3]);
                mma16816(acc[2*dp + 1], al, hb[2], hb[3]);
            }
        }
    }

    // ---- cross-warp reduction of 16 k-split segments ----
    __syncthreads();
    float* scr = (float*)Khi;                    // 16 segs x 16 rows x 68 stride
    #pragma unroll
    for (int nt = 0; nt < 8; ++nt) {
        const int d2 = nt * 8 + tg * 2;
        *(float2*)&scr[warp * 1088 +  g      * 68 + d2] = make_float2(acc[nt][0], acc[nt][1]);
        *(float2*)&scr[warp * 1088 + (g + 8) * 68 + d2] = make_float2(acc[nt][2], acc[nt][3]);
    }
    __syncthreads();

    {
        const int row = tid >> 5;                // 0..15
        const int dc  = (tid & 31) << 1;         // 0..62
        float2 s = {0.f, 0.f};
        #pragma unroll
        for (int w = 0; w < 16; ++w) {
            float2 v = *(float2*)&scr[w * 1088 + row * 68 + dc];
            s.x += v.x; s.y += v.y;
        }
        *(float2*)&ctx[qbase + (long)row * DH + dc] = s;
    }
}

extern "C" void kernel_launch(void* const* d_in, const int* in_sizes, int n_in,
                              void* d_out, int out_size)
{
    const float* Q = (const float*)d_in[0];
    const float* K = (const float*)d_in[1];
    const float* V = (const float*)d_in[2];

    float* ctx  = (float*)d_out;                         // [B,H,L,D]
    float* attn = ctx + (size_t)NBH * LSEQ * DH;         // [B,H,L,L]

    cudaFuncSetAttribute(sdpa_kernel,
                         cudaFuncAttributeMaxDynamicSharedMemorySize, SMEM_BYTES);

    dim3 grid(LSEQ / BQ, NBH);
    sdpa_kernel<<<grid, THREADS, SMEM_BYTES>>>(Q, K, V, ctx, attn);
}

// round 9
// speedup vs baseline: 3.7381x; 1.6247x over previous
#include <cuda_runtime.h>
#include <cuda_bf16.h>

#define BQ      16
#define LSEQ    2048
#define DH      64
#define CHUNK   128
#define NC      (LSEQ/CHUNK)    // 16
#define SSTR    2056            // S row stride (words)
#define QSTR    72              // bf16 row stride (elements)
#define NBH     64
#define THREADS 512

// smem: S[16][2056] f32 (131584) + Qhi/Qlo[16][72] (4608) + 2 stage bufs x (Khi+Klo)[128][72] (73728)
#define SMEM_BYTES (BQ*SSTR*4 + 2*BQ*QSTR*2 + 2*2*CHUNK*QSTR*2)   // 209920

// ---- global bf16 hi/lo planes for K and V (filled by pre-pass kernel) ----
__device__ __nv_bfloat16 gKhi[NBH*LSEQ*DH];
__device__ __nv_bfloat16 gKlo[NBH*LSEQ*DH];
__device__ __nv_bfloat16 gVhi[NBH*LSEQ*DH];
__device__ __nv_bfloat16 gVlo[NBH*LSEQ*DH];

__device__ __forceinline__ unsigned short bits(__nv_bfloat16 h) {
    return *reinterpret_cast<unsigned short*>(&h);
}

__device__ __forceinline__ void split4(float4 v, uint2& hi, uint2& lo) {
    __nv_bfloat16 h0 = __float2bfloat16_rn(v.x);
    __nv_bfloat16 h1 = __float2bfloat16_rn(v.y);
    __nv_bfloat16 h2 = __float2bfloat16_rn(v.z);
    __nv_bfloat16 h3 = __float2bfloat16_rn(v.w);
    __nv_bfloat16 l0 = __float2bfloat16_rn(v.x - __bfloat162float(h0));
    __nv_bfloat16 l1 = __float2bfloat16_rn(v.y - __bfloat162float(h1));
    __nv_bfloat16 l2 = __float2bfloat16_rn(v.z - __bfloat162float(h2));
    __nv_bfloat16 l3 = __float2bfloat16_rn(v.w - __bfloat162float(h3));
    hi.x = (unsigned)bits(h0) | ((unsigned)bits(h1) << 16);
    hi.y = (unsigned)bits(h2) | ((unsigned)bits(h3) << 16);
    lo.x = (unsigned)bits(l0) | ((unsigned)bits(l1) << 16);
    lo.y = (unsigned)bits(l2) | ((unsigned)bits(l3) << 16);
}

__device__ __forceinline__ void mma16816(float* d, const unsigned* a,
                                         unsigned b0, unsigned b1) {
    asm volatile(
        "mma.sync.aligned.m16n8k16.row.col.f32.bf16.bf16.f32 "
        "{%0,%1,%2,%3}, {%4,%5,%6,%7}, {%8,%9}, {%0,%1,%2,%3};"
        : "+f"(d[0]), "+f"(d[1]), "+f"(d[2]), "+f"(d[3])
        : "r"(a[0]), "r"(a[1]), "r"(a[2]), "r"(a[3]), "r"(b0), "r"(b1));
}

__device__ __forceinline__ void ldsm4(unsigned* r, const void* p) {
    unsigned addr = (unsigned)__cvta_generic_to_shared(p);
    asm volatile(
        "ldmatrix.sync.aligned.m8n8.x4.shared.b16 {%0,%1,%2,%3}, [%4];"
        : "=r"(r[0]), "=r"(r[1]), "=r"(r[2]), "=r"(r[3]) : "r"(addr));
}

__device__ __forceinline__ void ldsm4t(unsigned* r, const void* p) {
    unsigned addr = (unsigned)__cvta_generic_to_shared(p);
    asm volatile(
        "ldmatrix.sync.aligned.m8n8.x4.trans.shared.b16 {%0,%1,%2,%3}, [%4];"
        : "=r"(r[0]), "=r"(r[1]), "=r"(r[2]), "=r"(r[3]) : "r"(addr));
}

__device__ __forceinline__ void cp16(void* dst, const void* src) {
    unsigned d = (unsigned)__cvta_generic_to_shared(dst);
    asm volatile("cp.async.cg.shared.global [%0], [%1], 16;" :: "r"(d), "l"(src));
}
__device__ __forceinline__ void cp_commit() { asm volatile("cp.async.commit_group;"); }
__device__ __forceinline__ void cp_wait1()  { asm volatile("cp.async.wait_group 1;"); }
__device__ __forceinline__ void cp_wait0()  { asm volatile("cp.async.wait_group 0;"); }

// ==================== pre-pass: split K,V into bf16 hi/lo planes ====================
__global__ __launch_bounds__(256)
void convert_kv(const float4* __restrict__ K, const float4* __restrict__ V)
{
    int i = blockIdx.x * blockDim.x + threadIdx.x;   // over NBH*LSEQ*DH/4 = 2,097,152
    uint2 hi, lo;
    float4 k = K[i];
    split4(k, hi, lo);
    ((uint2*)gKhi)[i] = hi; ((uint2*)gKlo)[i] = lo;
    float4 v = V[i];
    split4(v, hi, lo);
    ((uint2*)gVhi)[i] = hi; ((uint2*)gVlo)[i] = lo;
}

// ==================== main kernel ====================
__global__ __launch_bounds__(THREADS, 1)
void sdpa_kernel(const float* __restrict__ Qg, float* __restrict__ ctx,
                 float* __restrict__ attn)
{
    extern __shared__ float sm[];
    float*          S    = sm;                                   // 16 x 2056 f32
    __nv_bfloat16*  Qhi  = (__nv_bfloat16*)(S + BQ * SSTR);      // 16 x 72
    __nv_bfloat16*  Qlo  = Qhi + BQ * QSTR;
    __nv_bfloat16*  Stage = Qlo + BQ * QSTR;                     // 4 planes of 128x72
    // buffer b: Hi plane = Stage + (2b)*CHUNK*QSTR ; Lo plane = Stage + (2b+1)*CHUNK*QSTR

    const int tid  = threadIdx.x;
    const int bh   = blockIdx.y;
    const int qt   = blockIdx.x;
    const long qbase  = ((long)bh * LSEQ + (long)qt * BQ) * DH;
    const long kvoff  = (long)bh * LSEQ * DH;

    const int warp = tid >> 5;      // 0..15
    const int lane = tid & 31;
    const int g    = lane >> 2;     // 0..7
    const int tg   = lane & 3;      // 0..3

    // staging index for cp.async (each thread copies 2x16B per plane per chunk)
    const int srow0 = tid >> 3;            // 0..63
    const int sc8   = (tid & 7) << 3;      // 0,8,...,56

    // ---- stage Q (first 256 threads) ----
    if (tid < 256) {
        int r  = tid >> 4;
        int d4 = (tid & 15) << 2;
        float4 v = *(const float4*)&Qg[qbase + (long)r * DH + d4];
        uint2 hi, lo; split4(v, hi, lo);
        *(uint2*)&Qhi[r * QSTR + d4] = hi;
        *(uint2*)&Qlo[r * QSTR + d4] = lo;
    }

    // ---- stage K chunk 0 into buffer 0 ----
    {
        __nv_bfloat16* bh_ = Stage;
        __nv_bfloat16* bl_ = Stage + CHUNK * QSTR;
        #pragma unroll
        for (int it = 0; it < 2; ++it) {
            int row = srow0 + it * 64;
            cp16(&bh_[row * QSTR + sc8], &gKhi[kvoff + (long)row * DH + sc8]);
            cp16(&bl_[row * QSTR + sc8], &gKlo[kvoff + (long)row * DH + sc8]);
        }
        cp_commit();
    }
    __syncthreads();    // Q planes visible to all

    // ---- hoist Q fragments (constant across all chunks) ----
    unsigned qh[4][4], ql[4][4];
    #pragma unroll
    for (int ks = 0; ks < 4; ++ks) {
        const int ko = ks * 16;
        qh[ks][0] = *(unsigned*)&Qhi[ g      * QSTR + ko + tg*2    ];
        qh[ks][1] = *(unsigned*)&Qhi[(g + 8) * QSTR + ko + tg*2    ];
        qh[ks][2] = *(unsigned*)&Qhi[ g      * QSTR + ko + tg*2 + 8];
        qh[ks][3] = *(unsigned*)&Qhi[(g + 8) * QSTR + ko + tg*2 + 8];
        ql[ks][0] = *(unsigned*)&Qlo[ g      * QSTR + ko + tg*2    ];
        ql[ks][1] = *(unsigned*)&Qlo[(g + 8) * QSTR + ko + tg*2    ];
        ql[ks][2] = *(unsigned*)&Qlo[ g      * QSTR + ko + tg*2 + 8];
        ql[ks][3] = *(unsigned*)&Qlo[(g + 8) * QSTR + ko + tg*2 + 8];
    }

    // ==================== Phase 1: S = Q @ K^T ====================
    // warp owns 8 keys per 128-key chunk
    {
        const int kb1 = warp * 8;
        // ldmatrix lane addressing (non-trans, x4: 8 rows x 32 cols per load)
        const int lrow8 = kb1 + (lane & 7);
        const int colg  = (lane >> 3) * 8;          // 0,8,16,24

        for (int c = 0; c < NC; ++c) {
            if (c + 1 < NC) {   // stage next chunk into alternate buffer
                __nv_bfloat16* bh_ = Stage + (2 * ((c + 1) & 1)) * CHUNK * QSTR;
                __nv_bfloat16* bl_ = bh_ + CHUNK * QSTR;
                const long gofs = kvoff + (long)(c + 1) * CHUNK * DH;
                #pragma unroll
                for (int it = 0; it < 2; ++it) {
                    int row = srow0 + it * 64;
                    cp16(&bh_[row * QSTR + sc8], &gKhi[gofs + (long)row * DH + sc8]);
                    cp16(&bl_[row * QSTR + sc8], &gKlo[gofs + (long)row * DH + sc8]);
                }
                cp_commit();
                cp_wait1();
            } else {
                cp_wait0();
            }
            __syncthreads();

            const __nv_bfloat16* KhiB = Stage + (2 * (c & 1)) * CHUNK * QSTR;
            const __nv_bfloat16* KloB = KhiB + CHUNK * QSTR;

            unsigned kh[2][4], kl[2][4];
            ldsm4(kh[0], &KhiB[lrow8 * QSTR +  0 + colg]);
            ldsm4(kh[1], &KhiB[lrow8 * QSTR + 32 + colg]);
            ldsm4(kl[0], &KloB[lrow8 * QSTR +  0 + colg]);
            ldsm4(kl[1], &KloB[lrow8 * QSTR + 32 + colg]);

            float a0[4] = {}, a1[4] = {}, a2[4] = {};   // 3 independent chains
            #pragma unroll
            for (int ks = 0; ks < 4; ++ks) {
                const unsigned* bb = &kh[ks >> 1][(ks & 1) * 2];
                const unsigned* bl = &kl[ks >> 1][(ks & 1) * 2];
                mma16816(a0, qh[ks], bb[0], bb[1]);   // hi*hi
                mma16816(a1, qh[ks], bl[0], bl[1]);   // hi*lo
                mma16816(a2, ql[ks], bb[0], bb[1]);   // lo*hi
            }
            const int col = c * CHUNK + kb1 + tg * 2;
            *(float2*)&S[ g      * SSTR + col] =
                make_float2(a0[0] + a1[0] + a2[0], a0[1] + a1[1] + a2[1]);
            *(float2*)&S[(g + 8) * SSTR + col] =
                make_float2(a0[2] + a1[2] + a2[2], a0[3] + a1[3] + a2[3]);
            __syncthreads();
        }
    }

    // ---- stage V chunk 0 (overlaps softmax) ----
    {
        __nv_bfloat16* bh_ = Stage;
        __nv_bfloat16* bl_ = Stage + CHUNK * QSTR;
        #pragma unroll
        for (int it = 0; it < 2; ++it) {
            int row = srow0 + it * 64;
            cp16(&bh_[row * QSTR + sc8], &gVhi[kvoff + (long)row * DH + sc8]);
            cp16(&bl_[row * QSTR + sc8], &gVlo[kvoff + (long)row * DH + sc8]);
        }
        cp_commit();
    }

    // ==================== Phase 2: softmax (1 row/warp); write attn; pack P hi|lo ====================
    {
        const int r = warp;
        float* Srow = S + r * SSTR;

        float m = -1e30f;
        for (int cc = lane * 4; cc < LSEQ; cc += 128) {
            float4 v = *(float4*)&Srow[cc];
            m = fmaxf(m, fmaxf(fmaxf(v.x, v.y), fmaxf(v.z, v.w)));
        }
        #pragma unroll
        for (int o = 16; o > 0; o >>= 1)
            m = fmaxf(m, __shfl_xor_sync(0xffffffffu, m, o));

        float sum = 0.f;
        for (int cc = lane * 4; cc < LSEQ; cc += 128) {
            float4 v = *(float4*)&Srow[cc];
            v.x = __expf(v.x - m); v.y = __expf(v.y - m);
            v.z = __expf(v.z - m); v.w = __expf(v.w - m);
            *(float4*)&Srow[cc] = v;
            sum += (v.x + v.y) + (v.z + v.w);
        }
        #pragma unroll
        for (int o = 16; o > 0; o >>= 1)
            sum += __shfl_xor_sync(0xffffffffu, sum, o);

        const float inv = 1.0f / sum;
        const long arow = ((long)bh * LSEQ + (long)qt * BQ + r) * LSEQ;
        for (int cc = lane * 4; cc < LSEQ; cc += 128) {
            float4 v = *(float4*)&Srow[cc];
            v.x *= inv; v.y *= inv; v.z *= inv; v.w *= inv;
            *(float4*)&attn[arow + cc] = v;
            uint2 hA, lA; split4(v, hA, lA);
            uint4 pk;
            pk.x = (hA.x & 0xffffu) | (lA.x << 16);
            pk.y = (hA.x >> 16)     | (lA.x & 0xffff0000u);
            pk.z = (hA.y & 0xffffu) | (lA.y << 16);
            pk.w = (hA.y >> 16)     | (lA.y & 0xffff0000u);
            *(uint4*)&Srow[cc] = pk;
        }
    }

    // ==================== Phase 3: ctx = P @ V ====================
    // warp -> (seg = warp&7 : 16-key segment, dhalf = warp>>3 : 32-dim half)
    float acc[4][4] = {};
    {
        const int seg   = warp & 7;
        const int dhalf = warp >> 3;
        const int kb    = seg * 16;
        const int lrow  = kb + (lane & 15);
        const int lcol  = (lane >> 4) * 8;

        for (int c = 0; c < NC; ++c) {
            if (c + 1 < NC) {
                __nv_bfloat16* bh_ = Stage + (2 * ((c + 1) & 1)) * CHUNK * QSTR;
                __nv_bfloat16* bl_ = bh_ + CHUNK * QSTR;
                const long gofs = kvoff + (long)(c + 1) * CHUNK * DH;
                #pragma unroll
                for (int it = 0; it < 2; ++it) {
                    int row = srow0 + it * 64;
                    cp16(&bh_[row * QSTR + sc8], &gVhi[gofs + (long)row * DH + sc8]);
                    cp16(&bl_[row * QSTR + sc8], &gVlo[gofs + (long)row * DH + sc8]);
                }
                cp_commit();
                cp_wait1();
            } else {
                cp_wait0();
            }
            __syncthreads();    // staged data visible; (iter0) softmax pack complete

            const __nv_bfloat16* VhiB = Stage + (2 * (c & 1)) * CHUNK * QSTR;
            const __nv_bfloat16* VloB = VhiB + CHUNK * QSTR;

            const int col = c * CHUNK + kb;
            uint2 w0 = *(uint2*)&S[ g      * SSTR + col + tg*2    ];
            uint2 w1 = *(uint2*)&S[(g + 8) * SSTR + col + tg*2    ];
            uint2 w2 = *(uint2*)&S[ g      * SSTR + col + tg*2 + 8];
            uint2 w3 = *(uint2*)&S[(g + 8) * SSTR + col + tg*2 + 8];
            unsigned ah[4], al[4];
            ah[0] = __byte_perm(w0.x, w0.y, 0x5410); al[0] = __byte_perm(w0.x, w0.y, 0x7632);
            ah[1] = __byte_perm(w1.x, w1.y, 0x5410); al[1] = __byte_perm(w1.x, w1.y, 0x7632);
            ah[2] = __byte_perm(w2.x, w2.y, 0x5410); al[2] = __byte_perm(w2.x, w2.y, 0x7632);
            ah[3] = __byte_perm(w3.x, w3.y, 0x5410); al[3] = __byte_perm(w3.x, w3.y, 0x7632);

            #pragma unroll
            for (int p = 0; p < 2; ++p) {           // two 16-dim groups in this half
                const int d0 = (dhalf * 2 + p) * 16;
                unsigned hb[4], lb[4];
                ldsm4t(hb, &VhiB[lrow * QSTR + d0 + lcol]);
                ldsm4t(lb, &VloB[lrow * QSTR + d0 + lcol]);
                mma16816(acc[2*p    ], ah, hb[0], hb[1]);
                mma16816(acc[2*p + 1], ah, hb[2], hb[3]);
                mma16816(acc[2*p    ], ah, lb[0], lb[1]);
                mma16816(acc[2*p + 1], ah, lb[2], lb[3]);
                mma16816(acc[2*p    ], al, hb[0], hb[1]);
                mma16816(acc[2*p + 1], al, hb[2], hb[3]);
            }
            __syncthreads();
        }
    }

    // ---- cross-warp reduction: 8 segments x 2 dim-halves ----
    // scr[16 slots][16 rows][36]; slot = (dhalf*8 + seg); local dims 0..31
    float* scr = (float*)Stage;
    {
        const int slot = (warp >> 3) * 8 + (warp & 7);
        #pragma unroll
        for (int nt = 0; nt < 4; ++nt) {
            const int d2 = nt * 8 + tg * 2;
            *(float2*)&scr[slot * 576 +  g      * 36 + d2] = make_float2(acc[nt][0], acc[nt][1]);
            *(float2*)&scr[slot * 576 + (g + 8) * 36 + d2] = make_float2(acc[nt][2], acc[nt][3]);
        }
    }
    __syncthreads();

    {
        const int row = tid >> 5;                // 0..15
        const int dc  = (tid & 31) << 1;         // 0..62
        const int base = (dc < 32) ? 0 : 8;
        const int dl   = dc & 31;
        float2 s = {0.f, 0.f};
        #pragma unroll
        for (int w = 0; w < 8; ++w) {
            float2 v = *(float2*)&scr[(base + w) * 576 + row * 36 + dl];
            s.x += v.x; s.y += v.y;
        }
        *(float2*)&ctx[qbase + (long)row * DH + dc] = s;
    }
}

extern "C" void kernel_launch(void* const* d_in, const int* in_sizes, int n_in,
                              void* d_out, int out_size)
{
    const float* Q = (const float*)d_in[0];
    const float* K = (const float*)d_in[1];
    const float* V = (const float*)d_in[2];

    float* ctx  = (float*)d_out;                         // [B,H,L,D]
    float* attn = ctx + (size_t)NBH * LSEQ * DH;         // [B,H,L,L]

    // pre-pass: split K,V into bf16 hi/lo planes
    convert_kv<<<(NBH*LSEQ*DH/4 + 255)/256, 256>>>((const float4*)K, (const float4*)V);

    cudaFuncSetAttribute(sdpa_kernel,
                         cudaFuncAttributeMaxDynamicSharedMemorySize, SMEM_BYTES);

    dim3 grid(LSEQ / BQ, NBH);
    sdpa_kernel<<<grid, THREADS, SMEM_BYTES>>>(Q, ctx, attn);
}

// round 10
// speedup vs baseline: 4.4295x; 1.1850x over previous
#include <cuda_runtime.h>
#include <cuda_bf16.h>

#define BQ      16
#define LSEQ    2048
#define DH      64
#define CHUNK   128
#define NC      (LSEQ/CHUNK)    // 16
#define SSTR    2056            // S row stride (words)
#define QSTR    72              // phase-1 bf16 row stride (elements)
#define VSTR    40              // phase-3 bf16 row stride (elements, 32 dims + pad)
#define NBH     64
#define THREADS 512

// per-warp stage region (bytes): max(phase1: 2 bufs * 2 planes * 8*72*2 = 4608,
//                                    phase3: 2 bufs * 2 planes * 16*40*2 = 5120)
#define WSTAGE  5120
// smem: S[16][2056] f32 (131584) + Qhi/Qlo[16][72] (4608) + 16 warp regions (81920)
#define SMEM_BYTES (BQ*SSTR*4 + 2*BQ*QSTR*2 + 16*WSTAGE)   // 218112

// ---- global bf16 hi/lo planes for K and V (filled by pre-pass kernel) ----
__device__ __nv_bfloat16 gKhi[NBH*LSEQ*DH];
__device__ __nv_bfloat16 gKlo[NBH*LSEQ*DH];
__device__ __nv_bfloat16 gVhi[NBH*LSEQ*DH];
__device__ __nv_bfloat16 gVlo[NBH*LSEQ*DH];

__device__ __forceinline__ unsigned short bits(__nv_bfloat16 h) {
    return *reinterpret_cast<unsigned short*>(&h);
}

__device__ __forceinline__ void split4(float4 v, uint2& hi, uint2& lo) {
    __nv_bfloat16 h0 = __float2bfloat16_rn(v.x);
    __nv_bfloat16 h1 = __float2bfloat16_rn(v.y);
    __nv_bfloat16 h2 = __float2bfloat16_rn(v.z);
    __nv_bfloat16 h3 = __float2bfloat16_rn(v.w);
    __nv_bfloat16 l0 = __float2bfloat16_rn(v.x - __bfloat162float(h0));
    __nv_bfloat16 l1 = __float2bfloat16_rn(v.y - __bfloat162float(h1));
    __nv_bfloat16 l2 = __float2bfloat16_rn(v.z - __bfloat162float(h2));
    __nv_bfloat16 l3 = __float2bfloat16_rn(v.w - __bfloat162float(h3));
    hi.x = (unsigned)bits(h0) | ((unsigned)bits(h1) << 16);
    hi.y = (unsigned)bits(h2) | ((unsigned)bits(h3) << 16);
    lo.x = (unsigned)bits(l0) | ((unsigned)bits(l1) << 16);
    lo.y = (unsigned)bits(l2) | ((unsigned)bits(l3) << 16);
}

__device__ __forceinline__ void mma16816(float* d, const unsigned* a,
                                         unsigned b0, unsigned b1) {
    asm volatile(
        "mma.sync.aligned.m16n8k16.row.col.f32.bf16.bf16.f32 "
        "{%0,%1,%2,%3}, {%4,%5,%6,%7}, {%8,%9}, {%0,%1,%2,%3};"
        : "+f"(d[0]), "+f"(d[1]), "+f"(d[2]), "+f"(d[3])
        : "r"(a[0]), "r"(a[1]), "r"(a[2]), "r"(a[3]), "r"(b0), "r"(b1));
}

__device__ __forceinline__ void ldsm4(unsigned* r, const void* p) {
    unsigned addr = (unsigned)__cvta_generic_to_shared(p);
    asm volatile(
        "ldmatrix.sync.aligned.m8n8.x4.shared.b16 {%0,%1,%2,%3}, [%4];"
        : "=r"(r[0]), "=r"(r[1]), "=r"(r[2]), "=r"(r[3]) : "r"(addr));
}

__device__ __forceinline__ void ldsm4t(unsigned* r, const void* p) {
    unsigned addr = (unsigned)__cvta_generic_to_shared(p);
    asm volatile(
        "ldmatrix.sync.aligned.m8n8.x4.trans.shared.b16 {%0,%1,%2,%3}, [%4];"
        : "=r"(r[0]), "=r"(r[1]), "=r"(r[2]), "=r"(r[3]) : "r"(addr));
}

__device__ __forceinline__ void cp16(void* dst, const void* src) {
    unsigned d = (unsigned)__cvta_generic_to_shared(dst);
    asm volatile("cp.async.cg.shared.global [%0], [%1], 16;" :: "r"(d), "l"(src));
}
__device__ __forceinline__ void cp_commit() { asm volatile("cp.async.commit_group;"); }
__device__ __forceinline__ void cp_wait1()  { asm volatile("cp.async.wait_group 1;"); }
__device__ __forceinline__ void cp_wait0()  { asm volatile("cp.async.wait_group 0;"); }

// ==================== pre-pass: split K,V into bf16 hi/lo planes ====================
__global__ __launch_bounds__(256)
void convert_kv(const float4* __restrict__ K, const float4* __restrict__ V)
{
    int i = blockIdx.x * blockDim.x + threadIdx.x;
    uint2 hi, lo;
    float4 k = K[i];
    split4(k, hi, lo);
    ((uint2*)gKhi)[i] = hi; ((uint2*)gKlo)[i] = lo;
    float4 v = V[i];
    split4(v, hi, lo);
    ((uint2*)gVhi)[i] = hi; ((uint2*)gVlo)[i] = lo;
}

// ==================== main kernel ====================
__global__ __launch_bounds__(THREADS, 1)
void sdpa_kernel(const float* __restrict__ Qg, float* __restrict__ ctx,
                 float* __restrict__ attn)
{
    extern __shared__ float sm[];
    float*          S    = sm;                                   // 16 x 2056 f32
    __nv_bfloat16*  Qhi  = (__nv_bfloat16*)(S + BQ * SSTR);      // 16 x 72
    __nv_bfloat16*  Qlo  = Qhi + BQ * QSTR;
    char*           StageBase = (char*)(Qlo + BQ * QSTR);        // 16 x WSTAGE

    const int tid  = threadIdx.x;
    const int bh   = blockIdx.y;
    const int qt   = blockIdx.x;
    const long qbase = ((long)bh * LSEQ + (long)qt * BQ) * DH;
    const long kvoff = (long)bh * LSEQ * DH;

    const int warp = tid >> 5;      // 0..15
    const int lane = tid & 31;
    const int g    = lane >> 2;     // 0..7
    const int tg   = lane & 3;      // 0..3

    char* wreg = StageBase + warp * WSTAGE;   // this warp's private stage region

    // ---- per-warp stagers (no block barriers needed) ----
    auto stageK = [&](int buf, int chunk) {
        __nv_bfloat16* bh_ = (__nv_bfloat16*)(wreg + buf * 2304);
        __nv_bfloat16* bl_ = (__nv_bfloat16*)(wreg + buf * 2304 + 1152);
        const long gofs = kvoff + (long)(chunk * CHUNK + warp * 8) * DH;
        #pragma unroll
        for (int p = 0; p < 2; ++p) {
            int idx = lane + p * 32;
            int row = idx >> 3, c8 = (idx & 7) << 3;
            cp16(&bh_[row * QSTR + c8], &gKhi[gofs + (long)row * DH + c8]);
            cp16(&bl_[row * QSTR + c8], &gKlo[gofs + (long)row * DH + c8]);
        }
        cp_commit();
    };

    const int seg   = warp & 7;     // phase-3: 16-key segment
    const int dhalf = warp >> 3;    // phase-3: 32-dim half

    auto stageV = [&](int buf, int chunk) {
        __nv_bfloat16* bh_ = (__nv_bfloat16*)(wreg + buf * 2560);
        __nv_bfloat16* bl_ = (__nv_bfloat16*)(wreg + buf * 2560 + 1280);
        const long gofs = kvoff + (long)(chunk * CHUNK + seg * 16) * DH + dhalf * 32;
        #pragma unroll
        for (int p = 0; p < 2; ++p) {
            int idx = lane + p * 32;
            int row = idx >> 2, c8 = (idx & 3) << 3;
            cp16(&bh_[row * VSTR + c8], &gVhi[gofs + (long)row * DH + c8]);
            cp16(&bl_[row * VSTR + c8], &gVlo[gofs + (long)row * DH + c8]);
        }
        cp_commit();
    };

    // ---- stage Q (first 256 threads) + K chunk 0 (per-warp) ----
    if (tid < 256) {
        int r  = tid >> 4;
        int d4 = (tid & 15) << 2;
        float4 v = *(const float4*)&Qg[qbase + (long)r * DH + d4];
        uint2 hi, lo; split4(v, hi, lo);
        *(uint2*)&Qhi[r * QSTR + d4] = hi;
        *(uint2*)&Qlo[r * QSTR + d4] = lo;
    }
    stageK(0, 0);
    __syncthreads();    // Q planes visible to all warps

    // ---- hoist Q fragments (constant across all chunks) ----
    unsigned qh[4][4], ql[4][4];
    #pragma unroll
    for (int ks = 0; ks < 4; ++ks) {
        const int ko = ks * 16;
        qh[ks][0] = *(unsigned*)&Qhi[ g      * QSTR + ko + tg*2    ];
        qh[ks][1] = *(unsigned*)&Qhi[(g + 8) * QSTR + ko + tg*2    ];
        qh[ks][2] = *(unsigned*)&Qhi[ g      * QSTR + ko + tg*2 + 8];
        qh[ks][3] = *(unsigned*)&Qhi[(g + 8) * QSTR + ko + tg*2 + 8];
        ql[ks][0] = *(unsigned*)&Qlo[ g      * QSTR + ko + tg*2    ];
        ql[ks][1] = *(unsigned*)&Qlo[(g + 8) * QSTR + ko + tg*2    ];
        ql[ks][2] = *(unsigned*)&Qlo[ g      * QSTR + ko + tg*2 + 8];
        ql[ks][3] = *(unsigned*)&Qlo[(g + 8) * QSTR + ko + tg*2 + 8];
    }

    // ==================== Phase 1: S = Q @ K^T  (barrier-free chunk loop) ====================
    {
        const int lr = lane & 7;
        const int cg = (lane >> 3) * 8;

        for (int c = 0; c < NC; ++c) {
            if (c + 1 < NC) { stageK((c + 1) & 1, c + 1); cp_wait1(); }
            else            { cp_wait0(); }
            // per-warp buffer: no cross-warp hazard, no __syncthreads

            const __nv_bfloat16* KhiB = (const __nv_bfloat16*)(wreg + (c & 1) * 2304);
            const __nv_bfloat16* KloB = (const __nv_bfloat16*)(wreg + (c & 1) * 2304 + 1152);

            unsigned kh[2][4], kl[2][4];
            ldsm4(kh[0], &KhiB[lr * QSTR +  0 + cg]);
            ldsm4(kh[1], &KhiB[lr * QSTR + 32 + cg]);
            ldsm4(kl[0], &KloB[lr * QSTR +  0 + cg]);
            ldsm4(kl[1], &KloB[lr * QSTR + 32 + cg]);

            float a0[4] = {}, a1[4] = {}, a2[4] = {};   // 3 independent chains
            #pragma unroll
            for (int ks = 0; ks < 4; ++ks) {
                const unsigned* bb = &kh[ks >> 1][(ks & 1) * 2];
                const unsigned* bl = &kl[ks >> 1][(ks & 1) * 2];
                mma16816(a0, qh[ks], bb[0], bb[1]);   // hi*hi
                mma16816(a1, qh[ks], bl[0], bl[1]);   // hi*lo
                mma16816(a2, ql[ks], bb[0], bb[1]);   // lo*hi
            }
            const int col = c * CHUNK + warp * 8 + tg * 2;
            *(float2*)&S[ g      * SSTR + col] =
                make_float2(a0[0] + a1[0] + a2[0], a0[1] + a1[1] + a2[1]);
            *(float2*)&S[(g + 8) * SSTR + col] =
                make_float2(a0[2] + a1[2] + a2[2], a0[3] + a1[3] + a2[3]);
        }
    }
    __syncthreads();    // S complete

    // stage V chunk 0 now — latency hidden behind softmax
    stageV(0, 0);

    // ==================== Phase 2: softmax (1 row/warp); write attn; pack P hi|lo ====================
    {
        const int r = warp;
        float* Srow = S + r * SSTR;

        float m = -1e30f;
        for (int cc = lane * 4; cc < LSEQ; cc += 128) {
            float4 v = *(float4*)&Srow[cc];
            m = fmaxf(m, fmaxf(fmaxf(v.x, v.y), fmaxf(v.z, v.w)));
        }
        #pragma unroll
        for (int o = 16; o > 0; o >>= 1)
            m = fmaxf(m, __shfl_xor_sync(0xffffffffu, m, o));

        float sum = 0.f;
        for (int cc = lane * 4; cc < LSEQ; cc += 128) {
            float4 v = *(float4*)&Srow[cc];
            v.x = __expf(v.x - m); v.y = __expf(v.y - m);
            v.z = __expf(v.z - m); v.w = __expf(v.w - m);
            *(float4*)&Srow[cc] = v;
            sum += (v.x + v.y) + (v.z + v.w);
        }
        #pragma unroll
        for (int o = 16; o > 0; o >>= 1)
            sum += __shfl_xor_sync(0xffffffffu, sum, o);

        const float inv = 1.0f / sum;
        const long arow = ((long)bh * LSEQ + (long)qt * BQ + r) * LSEQ;
        for (int cc = lane * 4; cc < LSEQ; cc += 128) {
            float4 v = *(float4*)&Srow[cc];
            v.x *= inv; v.y *= inv; v.z *= inv; v.w *= inv;
            *(float4*)&attn[arow + cc] = v;
            uint2 hA, lA; split4(v, hA, lA);
            uint4 pk;
            pk.x = (hA.x & 0xffffu) | (lA.x << 16);
            pk.y = (hA.x >> 16)     | (lA.x & 0xffff0000u);
            pk.z = (hA.y & 0xffffu) | (lA.y << 16);
            pk.w = (hA.y >> 16)     | (lA.y & 0xffff0000u);
            *(uint4*)&Srow[cc] = pk;
        }
    }
    __syncthreads();    // all rows softmaxed + packed

    // ==================== Phase 3: ctx = P @ V  (barrier-free chunk loop) ====================
    float acc[4][4] = {};
    {
        const int kb   = seg * 16;
        const int lrow = lane & 15;
        const int lcol = (lane >> 4) * 8;

        for (int c = 0; c < NC; ++c) {
            if (c + 1 < NC) { stageV((c + 1) & 1, c + 1); cp_wait1(); }
            else            { cp_wait0(); }

            const __nv_bfloat16* VhiB = (const __nv_bfloat16*)(wreg + (c & 1) * 2560);
            const __nv_bfloat16* VloB = (const __nv_bfloat16*)(wreg + (c & 1) * 2560 + 1280);

            const int col = c * CHUNK + kb;
            uint2 w0 = *(uint2*)&S[ g      * SSTR + col + tg*2    ];
            uint2 w1 = *(uint2*)&S[(g + 8) * SSTR + col + tg*2    ];
            uint2 w2 = *(uint2*)&S[ g      * SSTR + col + tg*2 + 8];
            uint2 w3 = *(uint2*)&S[(g + 8) * SSTR + col + tg*2 + 8];
            unsigned ah[4], al[4];
            ah[0] = __byte_perm(w0.x, w0.y, 0x5410); al[0] = __byte_perm(w0.x, w0.y, 0x7632);
            ah[1] = __byte_perm(w1.x, w1.y, 0x5410); al[1] = __byte_perm(w1.x, w1.y, 0x7632);
            ah[2] = __byte_perm(w2.x, w2.y, 0x5410); al[2] = __byte_perm(w2.x, w2.y, 0x7632);
            ah[3] = __byte_perm(w3.x, w3.y, 0x5410); al[3] = __byte_perm(w3.x, w3.y, 0x7632);

            #pragma unroll
            for (int p = 0; p < 2; ++p) {           // two local 16-dim groups
                const int d0 = p * 16;              // local dims within staged 32-dim half
                unsigned hb[4], lb[4];
                ldsm4t(hb, &VhiB[lrow * VSTR + d0 + lcol]);
                ldsm4t(lb, &VloB[lrow * VSTR + d0 + lcol]);
                mma16816(acc[2*p    ], ah, hb[0], hb[1]);
                mma16816(acc[2*p + 1], ah, hb[2], hb[3]);
                mma16816(acc[2*p    ], ah, lb[0], lb[1]);
                mma16816(acc[2*p + 1], ah, lb[2], lb[3]);
                mma16816(acc[2*p    ], al, hb[0], hb[1]);
                mma16816(acc[2*p + 1], al, hb[2], hb[3]);
            }
        }
    }

    // ---- cross-warp reduction: 8 segments x 2 dim-halves ----
    __syncthreads();    // all warps done with their stage regions (scr overlays them)
    float* scr = (float*)StageBase;          // 16 slots x 16 rows x 36 stride
    {
        const int slot = dhalf * 8 + seg;
        #pragma unroll
        for (int nt = 0; nt < 4; ++nt) {
            const int d2 = nt * 8 + tg * 2;
            *(float2*)&scr[slot * 576 +  g      * 36 + d2] = make_float2(acc[nt][0], acc[nt][1]);
            *(float2*)&scr[slot * 576 + (g + 8) * 36 + d2] = make_float2(acc[nt][2], acc[nt][3]);
        }
    }
    __syncthreads();

    {
        const int row = tid >> 5;                // 0..15
        const int dc  = (tid & 31) << 1;         // 0..62
        const int base = (dc < 32) ? 0 : 8;
        const int dl   = dc & 31;
        float2 s = {0.f, 0.f};
        #pragma unroll
        for (int w = 0; w < 8; ++w) {
            float2 v = *(float2*)&scr[(base + w) * 576 + row * 36 + dl];
            s.x += v.x; s.y += v.y;
        }
        *(float2*)&ctx[qbase + (long)row * DH + dc] = s;
    }
}

extern "C" void kernel_launch(void* const* d_in, const int* in_sizes, int n_in,
                              void* d_out, int out_size)
{
    const float* Q = (const float*)d_in[0];
    const float* K = (const float*)d_in[1];
    const float* V = (const float*)d_in[2];

    float* ctx  = (float*)d_out;                         // [B,H,L,D]
    float* attn = ctx + (size_t)NBH * LSEQ * DH;         // [B,H,L,L]

    convert_kv<<<(NBH*LSEQ*DH/4 + 255)/256, 256>>>((const float4*)K, (const float4*)V);

    cudaFuncSetAttribute(sdpa_kernel,
                         cudaFuncAttributeMaxDynamicSharedMemorySize, SMEM_BYTES);

    dim3 grid(LSEQ / BQ, NBH);
    sdpa_kernel<<<grid, THREADS, SMEM_BYTES>>>(Q, ctx, attn);
}